// round 1
// baseline (speedup 1.0000x reference)
#include <cuda_runtime.h>

#define NB 2
#define NM 8192
#define THREADS 256

// ---------------- scratch (device globals; no allocation) ----------------
__device__ unsigned long long g_keyA[2 * (642 + 2562 + 10242)]; // 26892: packed (dbits<<32 | m) per (lvl,b,v)
__device__ unsigned int       g_minB[3 * NB * NM];              // 49152: gt-side min bits per (lvl,b,m)
__device__ int                g_knn0[642 + 2562 + 10242];       // argmin for batch 0 only
__device__ double             g_acc[18];                        // 0-2 predsum 3-5 gtsum 6-8 edge 9-11 normal 12-14 lap 15-17 move

// ---------------- init ----------------
__global__ void init_kernel() {
    int i = blockIdx.x * blockDim.x + threadIdx.x;
    if (i < 26892) g_keyA[i] = ~0ULL;
    if (i < 3 * NB * NM) g_minB[i] = 0x7F800000u; // +inf bits (all d >= 0 after clamp)
    if (i < 18) g_acc[i] = 0.0;
}

// ---------------- pass A: per-pred min over M (+ argmin, first-index tiebreak) ----------------
__global__ void passA_kernel(const float* __restrict__ pred, const float* __restrict__ gt,
                             int V, int mlen, int keyOff)
{
    __shared__ float4 sg[256];
    const int b = blockIdx.z;
    const int t = threadIdx.x;
    const int i0 = blockIdx.x * (2 * THREADS) + t;
    const int i1 = i0 + THREADS;
    const int mbeg = blockIdx.y * mlen;
    if (mbeg >= NM) return;
    const int mend = min(mbeg + mlen, NM);

    const bool v0 = (i0 < V), v1 = (i1 < V);
    float px0 = 0.f, py0 = 0.f, pz0 = 0.f, px1 = 0.f, py1 = 0.f, pz1 = 0.f;
    if (v0) { const float* p = pred + ((size_t)b * V + i0) * 3; px0 = p[0]; py0 = p[1]; pz0 = p[2]; }
    if (v1) { const float* p = pred + ((size_t)b * V + i1) * 3; px1 = p[0]; py1 = p[1]; pz1 = p[2]; }
    const float p20 = px0 * px0 + py0 * py0 + pz0 * pz0;
    const float p21 = px1 * px1 + py1 * py1 + pz1 * pz1;
    const float ax0 = -2.f * px0, ay0 = -2.f * py0, az0 = -2.f * pz0;
    const float ax1 = -2.f * px1, ay1 = -2.f * py1, az1 = -2.f * pz1;

    float bd0 = 3.402823466e38f, bd1 = 3.402823466e38f;
    int bm0 = 0, bm1 = 0;

    for (int mt = mbeg; mt < mend; mt += 256) {
        const int n = min(256, mend - mt);
        __syncthreads();
        if (t < n) {
            const float* g = gt + ((size_t)b * NM + mt + t) * 3;
            float gx = g[0], gy = g[1], gz = g[2];
            sg[t] = make_float4(gx, gy, gz, gx * gx + gy * gy + gz * gz);
        }
        __syncthreads();
#pragma unroll 4
        for (int j = 0; j < n; j++) {
            float4 g = sg[j];
            float base0 = p20 + g.w;
            float d0 = fmaf(ax0, g.x, fmaf(ay0, g.y, fmaf(az0, g.z, base0)));
            if (d0 < bd0) { bd0 = d0; bm0 = mt + j; }
            float base1 = p21 + g.w;
            float d1 = fmaf(ax1, g.x, fmaf(ay1, g.y, fmaf(az1, g.z, base1)));
            if (d1 < bd1) { bd1 = d1; bm1 = mt + j; }
        }
    }
    if (v0) {
        unsigned long long key =
            ((unsigned long long)__float_as_uint(fmaxf(bd0, 0.f)) << 32) | (unsigned int)bm0;
        atomicMin(&g_keyA[keyOff + b * V + i0], key);
    }
    if (v1) {
        unsigned long long key =
            ((unsigned long long)__float_as_uint(fmaxf(bd1, 0.f)) << 32) | (unsigned int)bm1;
        atomicMin(&g_keyA[keyOff + b * V + i1], key);
    }
}

// ---------------- pass B: per-gt min over V ----------------
__global__ void passB_kernel(const float* __restrict__ pred, const float* __restrict__ gt,
                             int V, int vlen, int minOff)
{
    __shared__ float4 sp[256];
    const int b = blockIdx.z;
    const int t = threadIdx.x;
    const int j0 = blockIdx.x * (2 * THREADS) + t;  // 16 * 512 = 8192 exact
    const int j1 = j0 + THREADS;
    const int vbeg = blockIdx.y * vlen;
    if (vbeg >= V) return;
    const int vend = min(vbeg + vlen, V);

    const float* g0 = gt + ((size_t)b * NM + j0) * 3;
    const float* g1 = gt + ((size_t)b * NM + j1) * 3;
    float gx0 = g0[0], gy0 = g0[1], gz0 = g0[2];
    float gx1 = g1[0], gy1 = g1[1], gz1 = g1[2];
    const float q20 = gx0 * gx0 + gy0 * gy0 + gz0 * gz0;
    const float q21 = gx1 * gx1 + gy1 * gy1 + gz1 * gz1;
    const float ax0 = -2.f * gx0, ay0 = -2.f * gy0, az0 = -2.f * gz0;
    const float ax1 = -2.f * gx1, ay1 = -2.f * gy1, az1 = -2.f * gz1;

    float bd0 = 3.402823466e38f, bd1 = 3.402823466e38f;

    for (int vt = vbeg; vt < vend; vt += 256) {
        const int n = min(256, vend - vt);
        __syncthreads();
        if (t < n) {
            const float* p = pred + ((size_t)b * V + vt + t) * 3;
            float px = p[0], py = p[1], pz = p[2];
            sp[t] = make_float4(px, py, pz, px * px + py * py + pz * pz);
        }
        __syncthreads();
#pragma unroll 4
        for (int j = 0; j < n; j++) {
            float4 p = sp[j];
            float d0 = fmaf(ax0, p.x, fmaf(ay0, p.y, fmaf(az0, p.z, q20 + p.w)));
            bd0 = fminf(bd0, d0);
            float d1 = fmaf(ax1, p.x, fmaf(ay1, p.y, fmaf(az1, p.z, q21 + p.w)));
            bd1 = fminf(bd1, d1);
        }
    }
    atomicMin(&g_minB[minOff + b * NM + j0], __float_as_uint(fmaxf(bd0, 0.f)));
    atomicMin(&g_minB[minOff + b * NM + j1], __float_as_uint(fmaxf(bd1, 0.f)));
}

// ---------------- finalize A: sum pred-side mins, export knn for b=0 ----------------
__global__ void finA_kernel(int V, int keyOff, int knnOff, int accSlot)
{
    int idx = blockIdx.x * blockDim.x + threadIdx.x;
    float d = 0.f;
    if (idx < NB * V) {
        unsigned long long key = g_keyA[keyOff + idx];
        d = __uint_as_float((unsigned int)(key >> 32));
        int b = idx / V, v = idx - b * V;
        if (b == 0) g_knn0[knnOff + v] = (int)(key & 0xFFFFFFFFull);
    }
#pragma unroll
    for (int o = 16; o; o >>= 1) d += __shfl_down_sync(0xffffffffu, d, o);
    if ((threadIdx.x & 31) == 0) atomicAdd(&g_acc[accSlot], (double)d);
}

// ---------------- finalize B: sum gt-side mins ----------------
__global__ void finB_kernel(int minOff, int accSlot)
{
    int idx = blockIdx.x * blockDim.x + threadIdx.x;
    float d = 0.f;
    if (idx < NB * NM) d = __uint_as_float(g_minB[minOff + idx]);
#pragma unroll
    for (int o = 16; o; o >>= 1) d += __shfl_down_sync(0xffffffffu, d, o);
    if ((threadIdx.x & 31) == 0) atomicAdd(&g_acc[accSlot], (double)d);
}

// ---------------- edge + normal terms ----------------
__global__ void edge_kernel(const float* __restrict__ pred, const float* __restrict__ gtn,
                            const int* __restrict__ edges,
                            int V, int E, int knnOff, int slotEdge, int slotNrm)
{
    int idx = blockIdx.x * blockDim.x + threadIdx.x;
    float esum = 0.f, nsum = 0.f;
    if (idx < NB * E) {
        int b = idx / E, e = idx - b * E;
        int e0 = edges[2 * e], e1 = edges[2 * e + 1];
        const float* a = pred + ((size_t)b * V + e0) * 3;
        const float* c = pred + ((size_t)b * V + e1) * 3;
        float dx = a[0] - c[0], dy = a[1] - c[1], dz = a[2] - c[2];
        float sq = dx * dx + dy * dy + dz * dz;
        esum = sq;
        float inv = 1.f / fmaxf(sqrtf(sq), 1e-12f);
        int sel = g_knn0[knnOff + e0];
        const float* g = gtn + ((size_t)b * NM + sel) * 3;
        float gx = g[0], gy = g[1], gz = g[2];
        float gi = 1.f / fmaxf(sqrtf(gx * gx + gy * gy + gz * gz), 1e-12f);
        float dp = (dx * gx + dy * gy + dz * gz) * inv * gi;
        nsum = fabsf(dp);
    }
#pragma unroll
    for (int o = 16; o; o >>= 1) {
        esum += __shfl_down_sync(0xffffffffu, esum, o);
        nsum += __shfl_down_sync(0xffffffffu, nsum, o);
    }
    if ((threadIdx.x & 31) == 0) {
        atomicAdd(&g_acc[slotEdge], (double)esum);
        atomicAdd(&g_acc[slotNrm], (double)nsum);
    }
}

// ---------------- laplace + move terms ----------------
__global__ void lap_kernel(const float* __restrict__ pred, const float* __restrict__ before,
                           const int* __restrict__ lap,
                           int V, int slotLap, int slotMove, int doMove)
{
    int idx = blockIdx.x * blockDim.x + threadIdx.x;
    float lsum = 0.f, msum = 0.f;
    if (idx < NB * V) {
        int b = idx / V, v = idx - b * V;
        const int* row = lap + (size_t)v * 10;
        float cnt = (float)row[9];
        float sx = 0.f, sy = 0.f, sz = 0.f;
#pragma unroll
        for (int j = 0; j < 8; j++) {
            int id = row[j];
            if (id >= 0) {
                const float* pb = before + ((size_t)b * V + id) * 3;
                const float* pp = pred + ((size_t)b * V + id) * 3;
                sx += pb[0] - pp[0];
                sy += pb[1] - pp[1];
                sz += pb[2] - pp[2];
            }
        }
        const float* bv = before + ((size_t)b * V + v) * 3;
        const float* pv = pred + ((size_t)b * V + v) * 3;
        float dx = bv[0] - pv[0], dy = bv[1] - pv[1], dz = bv[2] - pv[2];
        float lx = dx - sx / cnt, ly = dy - sy / cnt, lz = dz - sz / cnt;
        lsum = lx * lx + ly * ly + lz * lz;
        msum = dx * dx + dy * dy + dz * dz;
    }
#pragma unroll
    for (int o = 16; o; o >>= 1) {
        lsum += __shfl_down_sync(0xffffffffu, lsum, o);
        msum += __shfl_down_sync(0xffffffffu, msum, o);
    }
    if ((threadIdx.x & 31) == 0) {
        atomicAdd(&g_acc[slotLap], (double)lsum);
        if (doMove) atomicAdd(&g_acc[slotMove], (double)msum);
    }
}

// ---------------- combine ----------------
__global__ void combine_kernel(float* out)
{
    const double Vd[3] = {642.0, 2562.0, 10242.0};
    const double Ed[3] = {1920.0, 7680.0, 30720.0};
    const double LAPC[3] = {0.2, 1.0, 1.0};
    double chamfer = 0, edge = 0, nrm = 0, lap = 0, move = 0;
    for (int i = 0; i < 3; i++) {
        chamfer += g_acc[3 + i] / (2.0 * 8192.0) + g_acc[i] / (2.0 * Vd[i]);
        edge += g_acc[6 + i] / (2.0 * Ed[i]);
        nrm += g_acc[9 + i] / (2.0 * Ed[i]);
        lap += LAPC[i] * g_acc[12 + i] / (2.0 * Vd[i]);
        if (i > 0) move += LAPC[i] * g_acc[15 + i] / (2.0 * Vd[i]);
    }
    out[0] = (float)(chamfer + 0.5 * lap + 0.1 * move + 0.1 * edge + 0.00016 * nrm);
}

// ---------------- launcher ----------------
extern "C" void kernel_launch(void* const* d_in, const int* in_sizes, int n_in,
                              void* d_out, int out_size)
{
    (void)out_size;
    const float *pred[3] = {0, 0, 0}, *before[3] = {0, 0, 0}, *gt = 0, *gtn = 0;
    const int *lap[3] = {0, 0, 0}, *edges[3] = {0, 0, 0};
    int c0 = 0, c1 = 0, c2 = 0, cg = 0;
    // Identify inputs purely by element count (robust to metadata ordering):
    // pred_coord precedes pred_before for each level, gt_coord precedes gt_normal.
    for (int i = 0; i < n_in; i++) {
        int s = in_sizes[i];
        const void* p = d_in[i];
        switch (s) {
            case 3852:  if (c0++ == 0) pred[0] = (const float*)p; else before[0] = (const float*)p; break;
            case 15372: if (c1++ == 0) pred[1] = (const float*)p; else before[1] = (const float*)p; break;
            case 61452: if (c2++ == 0) pred[2] = (const float*)p; else before[2] = (const float*)p; break;
            case 49152: if (cg++ == 0) gt = (const float*)p; else gtn = (const float*)p; break;
            case 6420:   lap[0] = (const int*)p; break;
            case 25620:  lap[1] = (const int*)p; break;
            case 102420: lap[2] = (const int*)p; break;
            case 3840:   edges[0] = (const int*)p; break;
            case 15360:  edges[1] = (const int*)p; break;
            case 61440:  edges[2] = (const int*)p; break;
            default: break;
        }
    }

    static const int V[3] = {642, 2562, 10242};
    static const int E[3] = {1920, 7680, 30720};
    static const int MSPLIT[3] = {160, 64, 16};  // keeps total blocks ~640-770 per level
    static const int VSPLIT[3] = {20, 20, 20};
    static const int keyOff[3] = {0, 2 * 642, 2 * 642 + 2 * 2562};
    static const int knnOff[3] = {0, 642, 642 + 2562};
    static const int minOff[3] = {0, 2 * NM, 4 * NM};

    init_kernel<<<(3 * NB * NM + 255) / 256, 256>>>();

    for (int i = 0; i < 3; i++) {
        int pChunks = (V[i] + 2 * THREADS - 1) / (2 * THREADS);
        int mlen = (NM + MSPLIT[i] - 1) / MSPLIT[i];
        passA_kernel<<<dim3(pChunks, MSPLIT[i], NB), THREADS>>>(pred[i], gt, V[i], mlen, keyOff[i]);

        int vlen = (V[i] + VSPLIT[i] - 1) / VSPLIT[i];
        passB_kernel<<<dim3(NM / (2 * THREADS), VSPLIT[i], NB), THREADS>>>(pred[i], gt, V[i], vlen, minOff[i]);

        finA_kernel<<<(NB * V[i] + 255) / 256, 256>>>(V[i], keyOff[i], knnOff[i], i);
        finB_kernel<<<(NB * NM + 255) / 256, 256>>>(minOff[i], 3 + i);

        edge_kernel<<<(NB * E[i] + 255) / 256, 256>>>(pred[i], gtn, edges[i], V[i], E[i], knnOff[i], 6 + i, 9 + i);
        lap_kernel<<<(NB * V[i] + 255) / 256, 256>>>(pred[i], before[i], lap[i], V[i], 12 + i, 15 + i, i > 0);
    }

    combine_kernel<<<1, 1>>>((float*)d_out);
}

// round 2
// speedup vs baseline: 1.8192x; 1.8192x over previous
#include <cuda_runtime.h>

#define NM 8192
#define NB 2
#define V0 642
#define V1 2562
#define V2 10242
#define E0 1920
#define E1 7680
#define E2 30720

// ---------------- scratch (device globals; no allocation) ----------------
__device__ unsigned long long g_keyA[NB * (V0 + V1 + V2)]; // packed (ordered_dbits<<32 | m)
__device__ unsigned int       g_minB[3 * NB * NM];         // ordered dbits per (lvl,b,m)
__device__ int                g_knn0[V0 + V1 + V2];        // argmin for batch 0
__device__ double             g_acc[18]; // 0-2 predsum 3-5 gtsum 6-8 edge 9-11 normal 12-14 lap 15-17 move

// ---------------- helpers ----------------
static __device__ __forceinline__ unsigned long long pack2(float lo, float hi) {
    unsigned long long r;
    asm("mov.b64 %0,{%1,%2};" : "=l"(r) : "f"(lo), "f"(hi));
    return r;
}
static __device__ __forceinline__ void unpack2(unsigned long long v, float& lo, float& hi) {
    asm("mov.b64 {%0,%1},%2;" : "=f"(lo), "=f"(hi) : "l"(v));
}
// packed dual-FMA: per-lane IEEE fma on two f32 packed in 64-bit regs (FFMA2)
static __device__ __forceinline__ unsigned long long fma2(unsigned long long a,
                                                          unsigned long long b,
                                                          unsigned long long c) {
    unsigned long long d;
    asm("fma.rn.f32x2 %0,%1,%2,%3;" : "=l"(d) : "l"(a), "l"(b), "l"(c));
    return d;
}
// monotone float -> uint transform (handles negatives) and inverse
static __device__ __forceinline__ unsigned int ford(float f) {
    unsigned int b = __float_as_uint(f);
    return b ^ (0x80000000u | (unsigned int)(((int)b) >> 31));
}
static __device__ __forceinline__ float funord(unsigned int u) {
    unsigned int b = (u & 0x80000000u) ? (u ^ 0x80000000u) : ~u;
    return __uint_as_float(b);
}

#define INF_F __int_as_float(0x7f800000)

// ---------------- init ----------------
__global__ void init_kernel() {
    int i = blockIdx.x * 256 + threadIdx.x; // grid = 192 blocks -> i < 49152
    if (i < NB * (V0 + V1 + V2)) g_keyA[i] = ~0ULL;
    g_minB[i] = 0xFFFFFFFFu;
    if (i < 18) g_acc[i] = 0.0;
}

// ---------------- chamfer inner loop (128 packed steps over a 256-pt tile) ----------------
template <bool ARGMIN>
static __device__ __forceinline__ void inner_loop(
    const ulonglong2* __restrict__ sXY, const ulonglong2* __restrict__ sZW,
    const unsigned long long* ax2, const unsigned long long* ay2, const unsigned long long* az2,
    float* bd, int* bm, int mbase)
{
#pragma unroll 4
    for (int j = 0; j < 128; j++) {
        ulonglong2 xy = sXY[j];
        ulonglong2 zw = sZW[j];
#pragma unroll
        for (int k = 0; k < 4; k++) {
            unsigned long long d = fma2(az2[k], zw.x, zw.y); // -2pz*gz + |g|^2
            d = fma2(ay2[k], xy.y, d);
            d = fma2(ax2[k], xy.x, d);
            float lo, hi;
            unpack2(d, lo, hi);
            if (ARGMIN) {
                if (lo < bd[k]) { bd[k] = lo; bm[k] = mbase + 2 * j; }
                if (hi < bd[k]) { bd[k] = hi; bm[k] = mbase + 2 * j + 1; }
            } else {
                bd[k] = fminf(bd[k], lo);
                bd[k] = fminf(bd[k], hi);
            }
        }
    }
}

// ---------------- fused chamfer (all levels, both directions, both batches) ----------------
// block map: [0,704)=A2 [704,1360)=B2 [1360,1552)=A1 [1552,1728)=B1 [1728,1792)=A0 [1792,1840)=B0
__global__ __launch_bounds__(256, 4) void chamfer_kernel(
    const float* __restrict__ p0l, const float* __restrict__ p1l, const float* __restrict__ p2l,
    const float* __restrict__ gt)
{
    __shared__ ulonglong2 sXY[128], sZW[128];
    const int id = blockIdx.x;
    const int t = threadIdx.x;

    int lvl, isA, u;
    if (id < 704)       { lvl = 2; isA = 1; u = id; }
    else if (id < 1360) { lvl = 2; isA = 0; u = id - 704; }
    else if (id < 1552) { lvl = 1; isA = 1; u = id - 1360; }
    else if (id < 1728) { lvl = 1; isA = 0; u = id - 1552; }
    else if (id < 1792) { lvl = 0; isA = 1; u = id - 1728; }
    else                { lvl = 0; isA = 0; u = id - 1792; }
    const int b = u & 1; u >>= 1;
    int chunk, slice;
    if (isA) { slice = u & 31; chunk = u >> 5; }   // 32 M-slices of 256
    else     { chunk = u & 7;  slice = u >> 3; }   // 8 M-chunks of 1024

    const float* pred = (lvl == 0) ? p0l : (lvl == 1 ? p1l : p2l);
    const int V = (lvl == 0) ? V0 : (lvl == 1 ? V1 : V2);

    unsigned long long ax2[4], ay2[4], az2[4];
    float bd[4] = {INF_F, INF_F, INF_F, INF_F};
    int bm[4] = {0, 0, 0, 0};

    if (isA) {
        // points = pred, loop dim = gt tile (always full 256)
        const int mtile = slice * 256;
        if (t < 128) {
            const float2* gp = (const float2*)(gt + ((size_t)b * NM + mtile) * 3);
            float2 f0 = gp[3 * t], f1 = gp[3 * t + 1], f2 = gp[3 * t + 2];
            float x0 = f0.x, y0 = f0.y, z0 = f1.x, x1 = f1.y, y1 = f2.x, z1 = f2.y;
            float w0 = x0 * x0 + y0 * y0 + z0 * z0;
            float w1 = x1 * x1 + y1 * y1 + z1 * z1;
            sXY[t] = make_ulonglong2(pack2(x0, x1), pack2(y0, y1));
            sZW[t] = make_ulonglong2(pack2(z0, z1), pack2(w0, w1));
        }
        const int vb = chunk * 1024 + t;
#pragma unroll
        for (int k = 0; k < 4; k++) {
            float px = 0.f, py = 0.f, pz = 0.f;
            int v = vb + 256 * k;
            if (v < V) {
                const float* pp = pred + ((size_t)b * V + v) * 3;
                px = pp[0]; py = pp[1]; pz = pp[2];
            }
            ax2[k] = pack2(-2.f * px, -2.f * px);
            ay2[k] = pack2(-2.f * py, -2.f * py);
            az2[k] = pack2(-2.f * pz, -2.f * pz);
        }
        __syncthreads();
        if (vb < V) {
            if (b == 0) inner_loop<true >(sXY, sZW, ax2, ay2, az2, bd, bm, mtile);
            else        inner_loop<false>(sXY, sZW, ax2, ay2, az2, bd, bm, mtile);
            const int keyOff = (lvl >= 1 ? NB * V0 : 0) + (lvl >= 2 ? NB * V1 : 0);
#pragma unroll
            for (int k = 0; k < 4; k++) {
                int v = vb + 256 * k;
                if (v < V) {
                    unsigned long long key =
                        ((unsigned long long)ford(bd[k]) << 32) | (unsigned int)bm[k];
                    atomicMin(&g_keyA[keyOff + b * V + v], key);
                }
            }
        }
    } else {
        // points = gt (always valid), loop dim = pred tile (pad tail with +inf)
        const int vtile = slice * 256;
        const int n = (V - vtile < 256) ? (V - vtile) : 256;
        if (t < 128) {
            float x0 = 0.f, y0 = 0.f, z0 = 0.f, w0 = INF_F;
            float x1 = 0.f, y1 = 0.f, z1 = 0.f, w1 = INF_F;
            int i0 = 2 * t, i1 = 2 * t + 1;
            if (i0 < n) {
                const float* pp = pred + ((size_t)b * V + vtile + i0) * 3;
                x0 = pp[0]; y0 = pp[1]; z0 = pp[2];
                w0 = x0 * x0 + y0 * y0 + z0 * z0;
            }
            if (i1 < n) {
                const float* pp = pred + ((size_t)b * V + vtile + i1) * 3;
                x1 = pp[0]; y1 = pp[1]; z1 = pp[2];
                w1 = x1 * x1 + y1 * y1 + z1 * z1;
            }
            sXY[t] = make_ulonglong2(pack2(x0, x1), pack2(y0, y1));
            sZW[t] = make_ulonglong2(pack2(z0, z1), pack2(w0, w1));
        }
        const int mb = chunk * 1024 + t;
#pragma unroll
        for (int k = 0; k < 4; k++) {
            const float* gp = gt + ((size_t)b * NM + mb + 256 * k) * 3;
            float gx = gp[0], gy = gp[1], gz = gp[2];
            ax2[k] = pack2(-2.f * gx, -2.f * gx);
            ay2[k] = pack2(-2.f * gy, -2.f * gy);
            az2[k] = pack2(-2.f * gz, -2.f * gz);
        }
        __syncthreads();
        inner_loop<false>(sXY, sZW, ax2, ay2, az2, bd, bm, vtile);
        const int minOff = lvl * NB * NM;
#pragma unroll
        for (int k = 0; k < 4; k++) {
            atomicMin(&g_minB[minOff + b * NM + mb + 256 * k], ford(bd[k]));
        }
    }
}

// ---------------- epilogue 1: finA (+knn) / finB / laplace+move, all levels ----------------
// blocks: finA [0,6)(L0) [6,27)(L1) [27,108)(L2); finB [108,172) [172,236) [236,300);
//         lap  [300,306) [306,327) [327,408)
__global__ void epi1_kernel(
    const float* __restrict__ p0l, const float* __restrict__ p1l, const float* __restrict__ p2l,
    const float* __restrict__ b0l, const float* __restrict__ b1l, const float* __restrict__ b2l,
    const int* __restrict__ l0l, const int* __restrict__ l1l, const int* __restrict__ l2l,
    const float* __restrict__ gt)
{
    const int bk = blockIdx.x, t = threadIdx.x;
    float val = 0.f, val2 = 0.f;
    int slot, slot2 = -1;

    if (bk < 108) {
        int lvl, base; const float* pred; int V, keyOff, knnOff;
        if (bk < 6)       { lvl = 0; base = bk * 256;        pred = p0l; V = V0; keyOff = 0;              knnOff = 0; }
        else if (bk < 27) { lvl = 1; base = (bk - 6) * 256;  pred = p1l; V = V1; keyOff = NB * V0;        knnOff = V0; }
        else              { lvl = 2; base = (bk - 27) * 256; pred = p2l; V = V2; keyOff = NB * (V0 + V1); knnOff = V0 + V1; }
        int idx = base + t;
        if (idx < NB * V) {
            unsigned long long key = g_keyA[keyOff + idx];
            int bb = idx / V, v = idx - bb * V;
            const float* pp = pred + ((size_t)bb * V + v) * 3;
            float p2 = pp[0] * pp[0] + pp[1] * pp[1] + pp[2] * pp[2];
            val = funord((unsigned int)(key >> 32)) + p2;
            if (bb == 0) g_knn0[knnOff + v] = (int)(key & 0xFFFFFFFFull);
        }
        slot = lvl;
    } else if (bk < 300) {
        int lvl = (bk - 108) >> 6;
        int idx = ((bk - 108) & 63) * 256 + t; // always < 16384
        unsigned int u = g_minB[lvl * NB * NM + idx];
        int bb = idx >> 13, m = idx & (NM - 1);
        const float* gp = gt + ((size_t)bb * NM + m) * 3;
        float g2 = gp[0] * gp[0] + gp[1] * gp[1] + gp[2] * gp[2];
        val = funord(u) + g2;
        slot = 3 + lvl;
    } else {
        int lvl, base; const float *pred, *bef; const int* lap; int V;
        if (bk < 306)      { lvl = 0; base = (bk - 300) * 256; pred = p0l; bef = b0l; lap = l0l; V = V0; }
        else if (bk < 327) { lvl = 1; base = (bk - 306) * 256; pred = p1l; bef = b1l; lap = l1l; V = V1; }
        else               { lvl = 2; base = (bk - 327) * 256; pred = p2l; bef = b2l; lap = l2l; V = V2; }
        int idx = base + t;
        if (idx < NB * V) {
            int bb = idx / V, v = idx - bb * V;
            const int* row = lap + (size_t)v * 10;
            float cnt = (float)row[9];
            float sx = 0.f, sy = 0.f, sz = 0.f;
#pragma unroll
            for (int j = 0; j < 8; j++) {
                int nid = row[j];
                if (nid >= 0) {
                    const float* pb = bef + ((size_t)bb * V + nid) * 3;
                    const float* pp = pred + ((size_t)bb * V + nid) * 3;
                    sx += pb[0] - pp[0];
                    sy += pb[1] - pp[1];
                    sz += pb[2] - pp[2];
                }
            }
            const float* bv = bef + ((size_t)bb * V + v) * 3;
            const float* pv = pred + ((size_t)bb * V + v) * 3;
            float dx = bv[0] - pv[0], dy = bv[1] - pv[1], dz = bv[2] - pv[2];
            float lx = dx - sx / cnt, ly = dy - sy / cnt, lz = dz - sz / cnt;
            val = lx * lx + ly * ly + lz * lz;
            val2 = dx * dx + dy * dy + dz * dz;
        }
        slot = 12 + lvl;
        if (lvl > 0) slot2 = 15 + lvl;
    }
#pragma unroll
    for (int o = 16; o; o >>= 1) {
        val  += __shfl_down_sync(0xffffffffu, val, o);
        val2 += __shfl_down_sync(0xffffffffu, val2, o);
    }
    if ((t & 31) == 0) {
        atomicAdd(&g_acc[slot], (double)val);
        if (slot2 >= 0) atomicAdd(&g_acc[slot2], (double)val2);
    }
}

// ---------------- epilogue 2: edge + normal, all levels ----------------
// blocks: [0,15)=L0 [15,75)=L1 [75,315)=L2
__global__ void epi2_kernel(
    const float* __restrict__ p0l, const float* __restrict__ p1l, const float* __restrict__ p2l,
    const float* __restrict__ gtn,
    const int* __restrict__ e0l, const int* __restrict__ e1l, const int* __restrict__ e2l)
{
    const int bk = blockIdx.x, t = threadIdx.x;
    int lvl, base; const float* pred; const int* edges; int V, E, knnOff;
    if (bk < 15)      { lvl = 0; base = bk * 256;        pred = p0l; edges = e0l; V = V0; E = E0; knnOff = 0; }
    else if (bk < 75) { lvl = 1; base = (bk - 15) * 256; pred = p1l; edges = e1l; V = V1; E = E1; knnOff = V0; }
    else              { lvl = 2; base = (bk - 75) * 256; pred = p2l; edges = e2l; V = V2; E = E2; knnOff = V0 + V1; }
    int idx = base + t;
    float esum = 0.f, nsum = 0.f;
    if (idx < NB * E) {
        int bb = idx / E, e = idx - bb * E;
        int e0 = edges[2 * e], e1 = edges[2 * e + 1];
        const float* a = pred + ((size_t)bb * V + e0) * 3;
        const float* c = pred + ((size_t)bb * V + e1) * 3;
        float dx = a[0] - c[0], dy = a[1] - c[1], dz = a[2] - c[2];
        float sq = dx * dx + dy * dy + dz * dz;
        esum = sq;
        float inv = 1.f / fmaxf(sqrtf(sq), 1e-12f);
        int sel = g_knn0[knnOff + e0];
        const float* g = gtn + ((size_t)bb * NM + sel) * 3;
        float gx = g[0], gy = g[1], gz = g[2];
        float gi = 1.f / fmaxf(sqrtf(gx * gx + gy * gy + gz * gz), 1e-12f);
        nsum = fabsf((dx * gx + dy * gy + dz * gz) * inv * gi);
    }
#pragma unroll
    for (int o = 16; o; o >>= 1) {
        esum += __shfl_down_sync(0xffffffffu, esum, o);
        nsum += __shfl_down_sync(0xffffffffu, nsum, o);
    }
    if ((t & 31) == 0) {
        atomicAdd(&g_acc[6 + lvl], (double)esum);
        atomicAdd(&g_acc[9 + lvl], (double)nsum);
    }
}

// ---------------- combine ----------------
__global__ void combine_kernel(float* out)
{
    const double Vd[3] = {642.0, 2562.0, 10242.0};
    const double Ed[3] = {1920.0, 7680.0, 30720.0};
    const double LAPC[3] = {0.2, 1.0, 1.0};
    double chamfer = 0, edge = 0, nrm = 0, lap = 0, move = 0;
    for (int i = 0; i < 3; i++) {
        chamfer += g_acc[3 + i] / (2.0 * 8192.0) + g_acc[i] / (2.0 * Vd[i]);
        edge += g_acc[6 + i] / (2.0 * Ed[i]);
        nrm += g_acc[9 + i] / (2.0 * Ed[i]);
        lap += LAPC[i] * g_acc[12 + i] / (2.0 * Vd[i]);
        if (i > 0) move += LAPC[i] * g_acc[15 + i] / (2.0 * Vd[i]);
    }
    out[0] = (float)(chamfer + 0.5 * lap + 0.1 * move + 0.1 * edge + 0.00016 * nrm);
}

// ---------------- launcher ----------------
extern "C" void kernel_launch(void* const* d_in, const int* in_sizes, int n_in,
                              void* d_out, int out_size)
{
    (void)out_size;
    const float *pred[3] = {0, 0, 0}, *before[3] = {0, 0, 0}, *gt = 0, *gtn = 0;
    const int *lap[3] = {0, 0, 0}, *edges[3] = {0, 0, 0};
    int c0 = 0, c1 = 0, c2 = 0, cg = 0;
    for (int i = 0; i < n_in; i++) {
        int s = in_sizes[i];
        const void* p = d_in[i];
        switch (s) {
            case 3852:  if (c0++ == 0) pred[0] = (const float*)p; else before[0] = (const float*)p; break;
            case 15372: if (c1++ == 0) pred[1] = (const float*)p; else before[1] = (const float*)p; break;
            case 61452: if (c2++ == 0) pred[2] = (const float*)p; else before[2] = (const float*)p; break;
            case 49152: if (cg++ == 0) gt = (const float*)p; else gtn = (const float*)p; break;
            case 6420:   lap[0] = (const int*)p; break;
            case 25620:  lap[1] = (const int*)p; break;
            case 102420: lap[2] = (const int*)p; break;
            case 3840:   edges[0] = (const int*)p; break;
            case 15360:  edges[1] = (const int*)p; break;
            case 61440:  edges[2] = (const int*)p; break;
            default: break;
        }
    }

    init_kernel<<<192, 256>>>();
    chamfer_kernel<<<1840, 256>>>(pred[0], pred[1], pred[2], gt);
    epi1_kernel<<<408, 256>>>(pred[0], pred[1], pred[2],
                              before[0], before[1], before[2],
                              lap[0], lap[1], lap[2], gt);
    epi2_kernel<<<315, 256>>>(pred[0], pred[1], pred[2], gtn,
                              edges[0], edges[1], edges[2]);
    combine_kernel<<<1, 1>>>((float*)d_out);
}

// round 3
// speedup vs baseline: 1.9269x; 1.0592x over previous
#include <cuda_runtime.h>

#define NM 8192
#define NB 2
#define V0 642
#define V1 2562
#define V2 10242
#define E0 1920
#define E1 7680
#define E2 30720

// ---------------- scratch (device globals; no allocation) ----------------
__device__ unsigned long long g_keyA[NB * (V0 + V1 + V2)]; // packed (ordered_dbits<<32 | m)
__device__ unsigned int       g_minB[3 * NB * NM];         // ordered dbits per (lvl,b,m)
__device__ double             g_acc[18]; // 0-2 predsum 3-5 gtsum 6-8 edge 9-11 normal 12-14 lap 15-17 move
__device__ unsigned int       g_done;

// ---------------- helpers ----------------
static __device__ __forceinline__ unsigned long long pack2(float lo, float hi) {
    unsigned long long r;
    asm("mov.b64 %0,{%1,%2};" : "=l"(r) : "f"(lo), "f"(hi));
    return r;
}
static __device__ __forceinline__ void unpack2(unsigned long long v, float& lo, float& hi) {
    asm("mov.b64 {%0,%1},%2;" : "=f"(lo), "=f"(hi) : "l"(v));
}
// packed dual-FMA: per-lane IEEE fma on two f32 packed in 64-bit regs (FFMA2)
static __device__ __forceinline__ unsigned long long fma2(unsigned long long a,
                                                          unsigned long long b,
                                                          unsigned long long c) {
    unsigned long long d;
    asm("fma.rn.f32x2 %0,%1,%2,%3;" : "=l"(d) : "l"(a), "l"(b), "l"(c));
    return d;
}
// monotone float -> uint transform (handles negatives) and inverse
static __device__ __forceinline__ unsigned int ford(float f) {
    unsigned int b = __float_as_uint(f);
    return b ^ (0x80000000u | (unsigned int)(((int)b) >> 31));
}
static __device__ __forceinline__ float funord(unsigned int u) {
    unsigned int b = (u & 0x80000000u) ? (u ^ 0x80000000u) : ~u;
    return __uint_as_float(b);
}

#define INF_F __int_as_float(0x7f800000)

// ---------------- init ----------------
__global__ void init_kernel() {
    int i = blockIdx.x * 256 + threadIdx.x; // grid = 192 blocks -> i < 49152
    if (i < NB * (V0 + V1 + V2)) g_keyA[i] = ~0ULL;
    g_minB[i] = 0xFFFFFFFFu;
    if (i < 18) g_acc[i] = 0.0;
    if (i == 0) g_done = 0u;
}

// ---------------- chamfer inner loop (128 packed steps over a 256-pt tile) ----------------
template <bool ARGMIN>
static __device__ __forceinline__ void inner_loop(
    const ulonglong2* __restrict__ sXY, const ulonglong2* __restrict__ sZW,
    const unsigned long long* ax2, const unsigned long long* ay2, const unsigned long long* az2,
    float* bd, int* bm, int mbase)
{
#pragma unroll 4
    for (int j = 0; j < 128; j++) {
        ulonglong2 xy = sXY[j];
        ulonglong2 zw = sZW[j];
#pragma unroll
        for (int k = 0; k < 4; k++) {
            unsigned long long d = fma2(az2[k], zw.x, zw.y); // -2pz*gz + |g|^2
            d = fma2(ay2[k], xy.y, d);
            d = fma2(ax2[k], xy.x, d);
            float lo, hi;
            unpack2(d, lo, hi);
            if (ARGMIN) {
                if (lo < bd[k]) { bd[k] = lo; bm[k] = mbase + 2 * j; }
                if (hi < bd[k]) { bd[k] = hi; bm[k] = mbase + 2 * j + 1; }
            } else {
                bd[k] = fminf(bd[k], lo);
                bd[k] = fminf(bd[k], hi);
            }
        }
    }
}

// ---------------- fused chamfer (all levels, both directions, both batches) ----------------
// block map: [0,704)=A2 [704,1360)=B2 [1360,1552)=A1 [1552,1728)=B1 [1728,1792)=A0 [1792,1840)=B0
__global__ __launch_bounds__(256, 4) void chamfer_kernel(
    const float* __restrict__ p0l, const float* __restrict__ p1l, const float* __restrict__ p2l,
    const float* __restrict__ gt)
{
    __shared__ ulonglong2 sXY[128], sZW[128];
    const int id = blockIdx.x;
    const int t = threadIdx.x;

    int lvl, isA, u;
    if (id < 704)       { lvl = 2; isA = 1; u = id; }
    else if (id < 1360) { lvl = 2; isA = 0; u = id - 704; }
    else if (id < 1552) { lvl = 1; isA = 1; u = id - 1360; }
    else if (id < 1728) { lvl = 1; isA = 0; u = id - 1552; }
    else if (id < 1792) { lvl = 0; isA = 1; u = id - 1728; }
    else                { lvl = 0; isA = 0; u = id - 1792; }
    const int b = u & 1; u >>= 1;
    int chunk, slice;
    if (isA) { slice = u & 31; chunk = u >> 5; }   // 32 M-slices of 256
    else     { chunk = u & 7;  slice = u >> 3; }   // 8 M-chunks of 1024

    const float* pred = (lvl == 0) ? p0l : (lvl == 1 ? p1l : p2l);
    const int V = (lvl == 0) ? V0 : (lvl == 1 ? V1 : V2);

    unsigned long long ax2[4], ay2[4], az2[4];
    float bd[4] = {INF_F, INF_F, INF_F, INF_F};
    int bm[4] = {0, 0, 0, 0};

    if (isA) {
        // points = pred, loop dim = gt tile (always full 256)
        const int mtile = slice * 256;
        if (t < 128) {
            const float2* gp = (const float2*)(gt + ((size_t)b * NM + mtile) * 3);
            float2 f0 = gp[3 * t], f1 = gp[3 * t + 1], f2 = gp[3 * t + 2];
            float x0 = f0.x, y0 = f0.y, z0 = f1.x, x1 = f1.y, y1 = f2.x, z1 = f2.y;
            float w0 = x0 * x0 + y0 * y0 + z0 * z0;
            float w1 = x1 * x1 + y1 * y1 + z1 * z1;
            sXY[t] = make_ulonglong2(pack2(x0, x1), pack2(y0, y1));
            sZW[t] = make_ulonglong2(pack2(z0, z1), pack2(w0, w1));
        }
        const int vb = chunk * 1024 + t;
#pragma unroll
        for (int k = 0; k < 4; k++) {
            float px = 0.f, py = 0.f, pz = 0.f;
            int v = vb + 256 * k;
            if (v < V) {
                const float* pp = pred + ((size_t)b * V + v) * 3;
                px = pp[0]; py = pp[1]; pz = pp[2];
            }
            ax2[k] = pack2(-2.f * px, -2.f * px);
            ay2[k] = pack2(-2.f * py, -2.f * py);
            az2[k] = pack2(-2.f * pz, -2.f * pz);
        }
        __syncthreads();
        if (vb < V) {
            if (b == 0) inner_loop<true >(sXY, sZW, ax2, ay2, az2, bd, bm, mtile);
            else        inner_loop<false>(sXY, sZW, ax2, ay2, az2, bd, bm, mtile);
            const int keyOff = (lvl >= 1 ? NB * V0 : 0) + (lvl >= 2 ? NB * V1 : 0);
#pragma unroll
            for (int k = 0; k < 4; k++) {
                int v = vb + 256 * k;
                if (v < V) {
                    unsigned long long key =
                        ((unsigned long long)ford(bd[k]) << 32) | (unsigned int)bm[k];
                    atomicMin(&g_keyA[keyOff + b * V + v], key);
                }
            }
        }
    } else {
        // points = gt (always valid), loop dim = pred tile (pad tail with +inf)
        const int vtile = slice * 256;
        const int n = (V - vtile < 256) ? (V - vtile) : 256;
        if (t < 128) {
            float x0 = 0.f, y0 = 0.f, z0 = 0.f, w0 = INF_F;
            float x1 = 0.f, y1 = 0.f, z1 = 0.f, w1 = INF_F;
            int i0 = 2 * t, i1 = 2 * t + 1;
            if (i0 < n) {
                const float* pp = pred + ((size_t)b * V + vtile + i0) * 3;
                x0 = pp[0]; y0 = pp[1]; z0 = pp[2];
                w0 = x0 * x0 + y0 * y0 + z0 * z0;
            }
            if (i1 < n) {
                const float* pp = pred + ((size_t)b * V + vtile + i1) * 3;
                x1 = pp[0]; y1 = pp[1]; z1 = pp[2];
                w1 = x1 * x1 + y1 * y1 + z1 * z1;
            }
            sXY[t] = make_ulonglong2(pack2(x0, x1), pack2(y0, y1));
            sZW[t] = make_ulonglong2(pack2(z0, z1), pack2(w0, w1));
        }
        const int mb = chunk * 1024 + t;
#pragma unroll
        for (int k = 0; k < 4; k++) {
            const float* gp = gt + ((size_t)b * NM + mb + 256 * k) * 3;
            float gx = gp[0], gy = gp[1], gz = gp[2];
            ax2[k] = pack2(-2.f * gx, -2.f * gx);
            ay2[k] = pack2(-2.f * gy, -2.f * gy);
            az2[k] = pack2(-2.f * gz, -2.f * gz);
        }
        __syncthreads();
        inner_loop<false>(sXY, sZW, ax2, ay2, az2, bd, bm, vtile);
        const int minOff = lvl * NB * NM;
#pragma unroll
        for (int k = 0; k < 4; k++) {
            atomicMin(&g_minB[minOff + b * NM + mb + 256 * k], ford(bd[k]));
        }
    }
}

// ---------------- merged epilogue: finA / finB / lap+move / edge+normal / combine ----------
// blocks: finA [0,6)(L0) [6,27)(L1) [27,108)(L2)
//         finB [108,172)(L0) [172,236)(L1) [236,300)(L2)
//         lap  [300,306)(L0) [306,327)(L1) [327,408)(L2)
//         edge [408,423)(L0) [423,483)(L1) [483,723)(L2)
// last finished block (ticket 722) computes the final scalar.
#define EPI_BLOCKS 723
__global__ __launch_bounds__(256) void epi_kernel(
    const float* __restrict__ p0l, const float* __restrict__ p1l, const float* __restrict__ p2l,
    const float* __restrict__ b0l, const float* __restrict__ b1l, const float* __restrict__ b2l,
    const int* __restrict__ l0l, const int* __restrict__ l1l, const int* __restrict__ l2l,
    const int* __restrict__ e0l, const int* __restrict__ e1l, const int* __restrict__ e2l,
    const float* __restrict__ gt, const float* __restrict__ gtn,
    float* __restrict__ out)
{
    const int bk = blockIdx.x, t = threadIdx.x;
    float val = 0.f, val2 = 0.f;
    int slot = -1, slot2 = -1;

    if (bk < 108) {
        // ---- finA: decode per-pred min keys, add back |p|^2 ----
        int lvl, base; const float* pred; int V, keyOff;
        if (bk < 6)       { lvl = 0; base = bk * 256;        pred = p0l; V = V0; keyOff = 0; }
        else if (bk < 27) { lvl = 1; base = (bk - 6) * 256;  pred = p1l; V = V1; keyOff = NB * V0; }
        else              { lvl = 2; base = (bk - 27) * 256; pred = p2l; V = V2; keyOff = NB * (V0 + V1); }
        int idx = base + t;
        if (idx < NB * V) {
            unsigned long long key = g_keyA[keyOff + idx];
            int bb = idx / V, v = idx - bb * V;
            const float* pp = pred + ((size_t)bb * V + v) * 3;
            float p2 = pp[0] * pp[0] + pp[1] * pp[1] + pp[2] * pp[2];
            val = funord((unsigned int)(key >> 32)) + p2;
        }
        slot = lvl;
    } else if (bk < 300) {
        // ---- finB: decode per-gt min, add back |g|^2 ----
        int lvl = (bk - 108) >> 6;
        int idx = ((bk - 108) & 63) * 256 + t; // always < 16384
        unsigned int u = g_minB[lvl * NB * NM + idx];
        int bb = idx >> 13, m = idx & (NM - 1);
        const float* gp = gt + ((size_t)bb * NM + m) * 3;
        float g2 = gp[0] * gp[0] + gp[1] * gp[1] + gp[2] * gp[2];
        val = funord(u) + g2;
        slot = 3 + lvl;
    } else if (bk < 408) {
        // ---- laplace + move ----
        int lvl, base; const float *pred, *bef; const int* lap; int V;
        if (bk < 306)      { lvl = 0; base = (bk - 300) * 256; pred = p0l; bef = b0l; lap = l0l; V = V0; }
        else if (bk < 327) { lvl = 1; base = (bk - 306) * 256; pred = p1l; bef = b1l; lap = l1l; V = V1; }
        else               { lvl = 2; base = (bk - 327) * 256; pred = p2l; bef = b2l; lap = l2l; V = V2; }
        int idx = base + t;
        if (idx < NB * V) {
            int bb = idx / V, v = idx - bb * V;
            const int* row = lap + (size_t)v * 10;
            float cnt = (float)row[9];
            float sx = 0.f, sy = 0.f, sz = 0.f;
#pragma unroll
            for (int j = 0; j < 8; j++) {
                int nid = row[j];
                if (nid >= 0) {
                    const float* pb = bef + ((size_t)bb * V + nid) * 3;
                    const float* pp = pred + ((size_t)bb * V + nid) * 3;
                    sx += pb[0] - pp[0];
                    sy += pb[1] - pp[1];
                    sz += pb[2] - pp[2];
                }
            }
            const float* bv = bef + ((size_t)bb * V + v) * 3;
            const float* pv = pred + ((size_t)bb * V + v) * 3;
            float dx = bv[0] - pv[0], dy = bv[1] - pv[1], dz = bv[2] - pv[2];
            float lx = dx - sx / cnt, ly = dy - sy / cnt, lz = dz - sz / cnt;
            val = lx * lx + ly * ly + lz * lz;
            val2 = dx * dx + dy * dy + dz * dz;
        }
        slot = 12 + lvl;
        if (lvl > 0) slot2 = 15 + lvl;
    } else {
        // ---- edge + normal (knn read straight from g_keyA low bits, batch 0) ----
        int lvl, base; const float* pred; const int* edges; int V, E, keyOff;
        if (bk < 423)      { lvl = 0; base = (bk - 408) * 256; pred = p0l; edges = e0l; V = V0; E = E0; keyOff = 0; }
        else if (bk < 483) { lvl = 1; base = (bk - 423) * 256; pred = p1l; edges = e1l; V = V1; E = E1; keyOff = NB * V0; }
        else               { lvl = 2; base = (bk - 483) * 256; pred = p2l; edges = e2l; V = V2; E = E2; keyOff = NB * (V0 + V1); }
        int idx = base + t;
        if (idx < NB * E) {
            int bb = idx / E, e = idx - bb * E;
            int e0 = edges[2 * e], e1 = edges[2 * e + 1];
            const float* a = pred + ((size_t)bb * V + e0) * 3;
            const float* c = pred + ((size_t)bb * V + e1) * 3;
            float dx = a[0] - c[0], dy = a[1] - c[1], dz = a[2] - c[2];
            float sq = dx * dx + dy * dy + dz * dz;
            val = sq;
            float inv = 1.f / fmaxf(sqrtf(sq), 1e-12f);
            int sel = (int)(unsigned int)(g_keyA[keyOff + e0] & 0xFFFFFFFFull); // batch-0 knn
            const float* g = gtn + ((size_t)bb * NM + sel) * 3;
            float gx = g[0], gy = g[1], gz = g[2];
            float gi = 1.f / fmaxf(sqrtf(gx * gx + gy * gy + gz * gz), 1e-12f);
            val2 = fabsf((dx * gx + dy * gy + dz * gz) * inv * gi);
        }
        slot = 6 + lvl;
        slot2 = 9 + lvl;
    }

#pragma unroll
    for (int o = 16; o; o >>= 1) {
        val  += __shfl_down_sync(0xffffffffu, val, o);
        val2 += __shfl_down_sync(0xffffffffu, val2, o);
    }
    if ((t & 31) == 0) {
        atomicAdd(&g_acc[slot], (double)val);
        if (slot2 >= 0) atomicAdd(&g_acc[slot2], (double)val2);
    }

    // ---- last-block combine ----
    __threadfence();
    __syncthreads();
    if (t == 0) {
        unsigned int ticket = atomicAdd(&g_done, 1u);
        if (ticket == EPI_BLOCKS - 1) {
            double a[18];
#pragma unroll
            for (int i = 0; i < 18; i++) a[i] = __ldcg(&g_acc[i]);
            const double Vd[3] = {642.0, 2562.0, 10242.0};
            const double Ed[3] = {1920.0, 7680.0, 30720.0};
            const double LAPC[3] = {0.2, 1.0, 1.0};
            double chamfer = 0, edge = 0, nrm = 0, lap = 0, move = 0;
            for (int i = 0; i < 3; i++) {
                chamfer += a[3 + i] / (2.0 * 8192.0) + a[i] / (2.0 * Vd[i]);
                edge += a[6 + i] / (2.0 * Ed[i]);
                nrm += a[9 + i] / (2.0 * Ed[i]);
                lap += LAPC[i] * a[12 + i] / (2.0 * Vd[i]);
                if (i > 0) move += LAPC[i] * a[15 + i] / (2.0 * Vd[i]);
            }
            out[0] = (float)(chamfer + 0.5 * lap + 0.1 * move + 0.1 * edge + 0.00016 * nrm);
        }
    }
}

// ---------------- launcher ----------------
extern "C" void kernel_launch(void* const* d_in, const int* in_sizes, int n_in,
                              void* d_out, int out_size)
{
    (void)out_size;
    const float *pred[3] = {0, 0, 0}, *before[3] = {0, 0, 0}, *gt = 0, *gtn = 0;
    const int *lap[3] = {0, 0, 0}, *edges[3] = {0, 0, 0};
    int c0 = 0, c1 = 0, c2 = 0, cg = 0;
    for (int i = 0; i < n_in; i++) {
        int s = in_sizes[i];
        const void* p = d_in[i];
        switch (s) {
            case 3852:  if (c0++ == 0) pred[0] = (const float*)p; else before[0] = (const float*)p; break;
            case 15372: if (c1++ == 0) pred[1] = (const float*)p; else before[1] = (const float*)p; break;
            case 61452: if (c2++ == 0) pred[2] = (const float*)p; else before[2] = (const float*)p; break;
            case 49152: if (cg++ == 0) gt = (const float*)p; else gtn = (const float*)p; break;
            case 6420:   lap[0] = (const int*)p; break;
            case 25620:  lap[1] = (const int*)p; break;
            case 102420: lap[2] = (const int*)p; break;
            case 3840:   edges[0] = (const int*)p; break;
            case 15360:  edges[1] = (const int*)p; break;
            case 61440:  edges[2] = (const int*)p; break;
            default: break;
        }
    }

    init_kernel<<<192, 256>>>();
    chamfer_kernel<<<1840, 256>>>(pred[0], pred[1], pred[2], gt);
    epi_kernel<<<EPI_BLOCKS, 256>>>(pred[0], pred[1], pred[2],
                                    before[0], before[1], before[2],
                                    lap[0], lap[1], lap[2],
                                    edges[0], edges[1], edges[2],
                                    gt, gtn, (float*)d_out);
}